// round 6
// baseline (speedup 1.0000x reference)
#include <cuda_runtime.h>
#include <cuda_fp16.h>
#include <cstdint>

#define CC 256
#define HWC 3136
#define MM 100352
typedef unsigned long long ull;

// ---------------- smem layout ----------------
#define PH    7680            /* params [0,7168) then HMMA buffers */
#define HSTR  40960           /* per-chunk HMMA stage: AH,AM,BH,BM */
#define AHO   0
#define AMO   10240
#define BHO   20480
#define BMO   30720
#define PF    89600           /* FFMA double buffer */
#define BDO   16384           /* Bdup offset inside FFMA stage */
#define FSTR  53248           /* 16384 A + 36864 Bdup */
#define SMEM_T (PF + 2*FSTR)  /* 196096 */
#define SCR_STR (128*34)      /* epilogue scratch row-pitch (floats) */

// ---------------- device scratch ----------------
__device__ __align__(16) float  g_buf[(size_t)CC*MM];
__device__ __align__(16) __half u_hi_d[CC*CC], u_mid_d[CC*CC];
__device__ __align__(16) __half ut_hi_d[CC*CC], ut_mid_d[CC*CC];
__device__ __align__(16) float  ut_f32_d[CC*CC];
__device__ float    chsum_d[CC];
__device__ unsigned gmax_d[CC], gmin_d[CC];
__device__ float    mn_d[CC], s_d[CC], dmin_d[CC], scale_d[CC], inv_d[CC], cvv_d[CC];
__device__ float    qsum_d[CC], bias_d[CC], same_d[CC];

// ---------------- helpers ----------------
__device__ __forceinline__ ull pk(float lo, float hi) {
    ull r; asm("mov.b64 %0, {%1,%2};" : "=l"(r) : "f"(lo), "f"(hi)); return r;
}
__device__ __forceinline__ ull dup2(float v) { return pk(v, v); }
__device__ __forceinline__ void fma2(ull& d, ull a, ull b) {
    asm("fma.rn.f32x2 %0, %1, %2, %0;" : "+l"(d) : "l"(a), "l"(b));
}
__device__ __forceinline__ void upk(ull v, float& lo, float& hi) {
    asm("mov.b64 {%0,%1}, %2;" : "=f"(lo), "=f"(hi) : "l"(v));
}
__device__ __forceinline__ void cp16(uint32_t sdst, const void* g) {
    asm volatile("cp.async.ca.shared.global [%0], [%1], 16;" :: "r"(sdst), "l"(g) : "memory");
}
__device__ __forceinline__ void cp_commit() { asm volatile("cp.async.commit_group;" ::: "memory"); }
__device__ __forceinline__ void cp_wait0()  { asm volatile("cp.async.wait_group 0;" ::: "memory"); }
__device__ __forceinline__ void ldsm4(unsigned* r, uint32_t addr) {
    asm volatile("ldmatrix.sync.aligned.m8n8.x4.shared.b16 {%0,%1,%2,%3}, [%4];"
        : "=r"(r[0]), "=r"(r[1]), "=r"(r[2]), "=r"(r[3]) : "r"(addr));
}
__device__ __forceinline__ void mma16816(float* d, const unsigned* a, const unsigned* b) {
    asm volatile("mma.sync.aligned.m16n8k16.row.col.f32.f16.f16.f32 "
        "{%0,%1,%2,%3}, {%4,%5,%6,%7}, {%8,%9}, {%0,%1,%2,%3};"
        : "+f"(d[0]), "+f"(d[1]), "+f"(d[2]), "+f"(d[3])
        : "r"(a[0]), "r"(a[1]), "r"(a[2]), "r"(a[3]), "r"(b[0]), "r"(b[1]));
}
__device__ __forceinline__ unsigned encf(float f) {
    unsigned u = __float_as_uint(f);
    return (u & 0x80000000u) ? ~u : (u | 0x80000000u);
}
__device__ __forceinline__ float decf(unsigned u) {
    unsigned b = (u & 0x80000000u) ? (u & 0x7FFFFFFFu) : ~u;
    return __uint_as_float(b);
}
__device__ __forceinline__ float quant1(float g, float s, float dm, float sc, float iv,
                                        float cv, float sm) {
    float val = fminf(fmaxf(g - s, -cv), cv);
    float qq  = rintf((val - dm) * sc) * iv + dm;
    return (sm > 0.5f) ? val : qq;
}

// ---------------- prep ----------------
__global__ void prep_k(const float* __restrict__ u) {
    int t = threadIdx.x, b = blockIdx.x;
    if (b < CC) {
        float val = u[(size_t)b*CC + t];                 // u[c=b][j=t]
        __half h = __float2half_rn(val);
        __half e = __float2half_rn(val - __half2float(h));   // unscaled residual
        u_hi_d [b*CC + t] = h;  u_mid_d [b*CC + t] = e;      // [c][j]
        ut_hi_d[t*CC + b] = h;  ut_mid_d[t*CC + b] = e;      // [j][c]
        ut_f32_d[t*CC + b] = val;                            // [j][c] fp32
    } else {
        chsum_d[t] = 0.0f; qsum_d[t] = 0.0f;
        gmax_d[t] = 0u; gmin_d[t] = 0xFFFFFFFFu;
    }
}

// ---------------- FFMA chunk producer (fp32 staging) ----------------
// Stages chunk f (k = f*32..+32): A [32k][128m] fp32, B dup-pairs [32k][8 grp][16+2 ull]
template<int MODE>
__device__ void prodF(char* smem, const float* __restrict__ X, const float* __restrict__ U,
                      int m0, int by, int f, int st, int tl, int TL)
{
    const int kb = f*32;
    const int lane = tl & 31;
    float* afp = (float*)(smem + PF + st*FSTR);
    ull*   bdp = (ull*)  (smem + PF + st*FSTR + BDO);
    const float* ps = (const float*)smem;

    // A: 1024 float4 tasks (row = k-slice, seg = m/4)
    for (int idx = tl; idx < 1024; idx += TL) {
        int row = idx >> 5, seg = idx & 31;
        int c = kb + row;
        int m = m0 + seg*4;
        float4 v;
        if (!MODE) {
            int img = m / HWC;
            v = *(const float4*)(X + (size_t)img*(CC*HWC) + (size_t)c*HWC + (m - img*HWC));
            v.x = fmaxf(v.x, 0.f); v.y = fmaxf(v.y, 0.f);
            v.z = fmaxf(v.z, 0.f); v.w = fmaxf(v.w, 0.f);
            float s = v.x + v.y + v.z + v.w;
            #pragma unroll
            for (int d = 1; d < 32; d <<= 1) s += __shfl_xor_sync(~0u, s, d);
            if (by == 0 && lane == 0) atomicAdd(&chsum_d[c], s);  // row constant per warp-iter
        } else {
            v = *(const float4*)(g_buf + (size_t)c*MM + m);
            float S=ps[c], DM=ps[256+c], SC=ps[512+c], IV=ps[768+c], CV=ps[1024+c], SM=ps[1280+c];
            v.x = quant1(v.x, S, DM, SC, IV, CV, SM);
            v.y = quant1(v.y, S, DM, SC, IV, CV, SM);
            v.z = quant1(v.z, S, DM, SC, IV, CV, SM);
            v.w = quant1(v.w, S, DM, SC, IV, CV, SM);
        }
        *(float4*)(afp + row*128 + seg*4) = v;
    }
    // B: 1024 float4 tasks -> duplicated pairs
    for (int idx = tl; idx < 1024; idx += TL) {
        int row = idx >> 5, seg = idx & 31;
        const float* src = MODE ? (ut_f32_d + (size_t)(kb+row)*CC + by*128 + seg*4)
                                : (U        + (size_t)(kb+row)*CC + by*128 + seg*4);
        float4 v = *(const float4*)src;
        int g = seg >> 2, wi = (seg & 3) * 4;
        ull* d = bdp + (size_t)row*144 + g*18 + wi;
        ulonglong2 t0; t0.x = dup2(v.x); t0.y = dup2(v.y);
        ulonglong2 t1; t1.x = dup2(v.z); t1.y = dup2(v.w);
        *(ulonglong2*)(d)     = t0;
        *(ulonglong2*)(d + 2) = t1;
    }
}

// ---------------- HMMA staging (chunks 0,1; all 256 threads) ----------------
template<int MODE>
__device__ void stageH(char* smem, uint32_t sb, const float* __restrict__ X, int m0, int by, int tid)
{
    const int lane = tid & 31;
    const int mg = tid & 15, cp = tid >> 4;       // 8-m group, k-pair
    const int mrow = m0 + mg*8;
    size_t abase = 0;
    if (!MODE) { int img = mrow / HWC; abase = (size_t)img*(CC*HWC) + (mrow - img*HWC); }
    const float* ps = (const float*)smem;

    #pragma unroll
    for (int ch = 0; ch < 2; ch++) {
        char* hb = smem + PH + ch*HSTR;
        float v[2][8];
        #pragma unroll
        for (int cc = 0; cc < 2; cc++) {
            int c = ch*32 + cp*2 + cc;
            const float4* p = MODE ? (const float4*)(g_buf + (size_t)c*MM + mrow)
                                   : (const float4*)(X + abase + (size_t)c*HWC);
            float4 q0 = p[0], q1 = p[1];
            v[cc][0]=q0.x; v[cc][1]=q0.y; v[cc][2]=q0.z; v[cc][3]=q0.w;
            v[cc][4]=q1.x; v[cc][5]=q1.y; v[cc][6]=q1.z; v[cc][7]=q1.w;
            if (!MODE) {
                float s = 0.f;
                #pragma unroll
                for (int i = 0; i < 8; i++) { v[cc][i] = fmaxf(v[cc][i], 0.f); s += v[cc][i]; }
                s += __shfl_xor_sync(~0u, s, 1); s += __shfl_xor_sync(~0u, s, 2);
                s += __shfl_xor_sync(~0u, s, 4); s += __shfl_xor_sync(~0u, s, 8);
                if (by == 0 && (lane & 15) == 0) atomicAdd(&chsum_d[c], s);
            } else {
                float S=ps[c], DM=ps[256+c], SC=ps[512+c], IV=ps[768+c], CV=ps[1024+c], SM=ps[1280+c];
                #pragma unroll
                for (int i = 0; i < 8; i++) v[cc][i] = quant1(v[cc][i], S, DM, SC, IV, CV, SM);
            }
        }
        #pragma unroll
        for (int i = 0; i < 8; i++) {
            __half h0 = __float2half_rn(v[0][i]);
            __half h1 = __float2half_rn(v[1][i]);
            __half e0 = __float2half_rn(v[0][i] - __half2float(h0));
            __half e1 = __float2half_rn(v[1][i] - __half2float(h1));
            uint32_t off = (uint32_t)(((mg*8 + i)*40 + cp*2) * 2);
            *(__half2*)(hb + AHO + off) = __halves2half2(h0, h1);
            *(__half2*)(hb + AMO + off) = __halves2half2(e0, e1);
        }
        // B fp16 tiles via cp.async: 1024 16B units (512 hi + 512 mid)
        #pragma unroll
        for (int i = 0; i < 4; i++) {
            int ui = tid + i*256;
            int ish = (ui < 512);
            int r = (ui & 511) >> 2;
            int q = ui & 3;
            uint32_t dst = sb + PH + ch*HSTR + (ish ? BHO : BMO) + (uint32_t)(r*80 + q*16);
            const __half* src = (ish ? (MODE ? u_hi_d : ut_hi_d) : (MODE ? u_mid_d : ut_mid_d))
                              + (size_t)(by*128 + r)*CC + ch*32 + q*8;
            cp16(dst, src);
        }
    }
    cp_commit();
}

// ---------------- hybrid GEMM ----------------
// MODE 0: g = u^T relu(x)  (+chsum, per-j max/min)
// MODE 1: out = u q + bias  (NCHW scatter)
template<int MODE>
__global__ void __launch_bounds__(256, 1)
hgemm_k(const float* __restrict__ X, const float* __restrict__ U, float* __restrict__ OUT)
{
    extern __shared__ char smem[];
    const uint32_t sb = (uint32_t)__cvta_generic_to_shared(smem);
    const int tid = threadIdx.x, lane = tid & 31, w = tid >> 5;
    const int m0 = blockIdx.x * 128;
    const int by = blockIdx.y;
    float* ps = (float*)smem;

    if (MODE) {
        ps[tid]        = s_d[tid];     ps[256 + tid]  = dmin_d[tid];
        ps[512 + tid]  = scale_d[tid]; ps[768 + tid]  = inv_d[tid];
        ps[1024 + tid] = cvv_d[tid];   ps[1280 + tid] = same_d[tid];
        ps[1536 + tid] = bias_d[tid];
    }
    __syncthreads();

    // Phase A: stage HMMA chunks 0,1 + FFMA chunk 2 (all threads)
    stageH<MODE>(smem, sb, X, m0, by, tid);
    prodF<MODE>(smem, X, U, m0, by, 2, 0, tid, 256);
    cp_wait0();
    __syncthreads();

    if (w < 4) {
        // ============ P-warp: producer + HMMA (m-strip = w*32, all 128 n, kH=64) ============
        const int pw = w;
        float acc[2][16][4];
        #pragma unroll
        for (int a = 0; a < 2; a++)
            #pragma unroll
            for (int b = 0; b < 16; b++)
                #pragma unroll
                for (int c = 0; c < 4; c++) acc[a][b][c] = 0.f;

        const int arow = lane & 15, asel = (lane >> 4) << 3;
        const int brow = (lane & 7) + ((lane >> 4) << 3), bsel = ((lane >> 3) & 1) << 3;

        for (int f = 2; f < 8; f++) {
            if (f < 7) prodF<MODE>(smem, X, U, m0, by, f + 1, (f & 1) ^ 1, tid, 128);
            const int blk = f - 2;
            if (blk < 4) {
                const int ch = blk >> 1, kb = (blk & 1) * 16;
                const uint32_t hbase = sb + PH + ch*HSTR;
                unsigned ah[2][4], am[2][4];
                #pragma unroll
                for (int mt = 0; mt < 2; mt++) {
                    uint32_t ra = hbase + AHO + (uint32_t)(((pw*32 + mt*16 + arow)*40 + kb + asel)*2);
                    ldsm4(ah[mt], ra);
                    ldsm4(am[mt], ra + (AMO - AHO));
                }
                #pragma unroll
                for (int ng = 0; ng < 8; ng++) {
                    uint32_t rb = hbase + BHO + (uint32_t)(((ng*16 + brow)*40 + kb + bsel)*2);
                    unsigned bh[4], bm[4];
                    ldsm4(bh, rb);
                    ldsm4(bm, rb + (BMO - BHO));
                    #pragma unroll
                    for (int mt = 0; mt < 2; mt++) {
                        mma16816(acc[mt][ng*2],     ah[mt], bh);
                        mma16816(acc[mt][ng*2 + 1], ah[mt], bh + 2);
                        mma16816(acc[mt][ng*2],     ah[mt], bm);      // a0*(b-b0)
                        mma16816(acc[mt][ng*2 + 1], ah[mt], bm + 2);
                        mma16816(acc[mt][ng*2],     am[mt], bh);      // (a-a0)*b0
                        mma16816(acc[mt][ng*2 + 1], am[mt], bh + 2);
                    }
                }
            }
            __syncthreads();
        }
        // write HMMA partial to scratch (reuses FFMA buffer region)
        float* scr = (float*)(smem + PF) + pw * SCR_STR;
        #pragma unroll
        for (int mt = 0; mt < 2; mt++)
            #pragma unroll
            for (int nt = 0; nt < 16; nt++)
                #pragma unroll
                for (int i = 0; i < 4; i++) {
                    int nl = nt*8 + (lane & 3)*2 + (i & 1);
                    int ml = mt*16 + (lane >> 2) + ((i >> 1) << 3);
                    scr[nl*34 + ml] = acc[mt][nt][i];
                }
    } else {
        // ============ F-warp: pure FFMA2 (m-strip = (w-4)*32, all 128 n, kF=192) ============
        const int fw = w - 4;
        const int tm = (lane & 3) * 8, tnr = lane >> 2;
        ull acc[4][16];
        #pragma unroll
        for (int p = 0; p < 4; p++)
            #pragma unroll
            for (int q = 0; q < 16; q++) acc[p][q] = 0ull;

        for (int f = 2; f < 8; f++) {
            const int st = f & 1;
            const float* afp = (const float*)(smem + PF + st*FSTR) + fw*32 + tm;
            const ull*   bdp = (const ull*)(smem + PF + st*FSTR + BDO) + tnr*18;
            #pragma unroll 4
            for (int k = 0; k < 32; k++) {
                ulonglong2 a01 = *(const ulonglong2*)(afp + k*128);
                ulonglong2 a23 = *(const ulonglong2*)(afp + k*128 + 4);
                ull a[4] = { a01.x, a01.y, a23.x, a23.y };
                ull b[16];
                #pragma unroll
                for (int i = 0; i < 8; i++) {
                    ulonglong2 t = *(const ulonglong2*)(bdp + (size_t)k*144 + i*2);
                    b[2*i] = t.x; b[2*i + 1] = t.y;
                }
                #pragma unroll
                for (int p = 0; p < 4; p++)
                    #pragma unroll
                    for (int q = 0; q < 16; q++)
                        fma2(acc[p][q], a[p], b[q]);
            }
            __syncthreads();
        }
        // nothing yet — merge after barrier
        // (keep acc live)
        float* scr = (float*)(smem + PF) + fw * SCR_STR;
        __syncthreads();   // barrier #7: P-warps wrote scr
        #pragma unroll
        for (int p = 0; p < 4; p++)
            #pragma unroll
            for (int q = 0; q < 16; q++) {
                float lo, hi; upk(acc[p][q], lo, hi);
                float2* d = (float2*)(scr + (tnr*16 + q)*34 + tm + 2*p);
                float2 old = *d;
                old.x += lo; old.y += hi;
                *d = old;
            }
    }
    // matching barrier #7 for P-warps (F-warps already executed theirs above)
    if (w < 4) __syncthreads();
    __syncthreads();   // barrier #8: merge complete

    // ---------------- final pass: all 8 warps ----------------
    #pragma unroll 1
    for (int jj = 0; jj < 16; jj++) {
        int j = w*16 + jj;
        #pragma unroll
        for (int s = 0; s < 4; s++) {
            const float* scr_s = (const float*)(smem + PF) + s * SCR_STR;
            float val = scr_s[j*34 + lane];
            if (!MODE) {
                float mx = val, mn = val;
                #pragma unroll
                for (int d = 1; d < 32; d <<= 1) {
                    mx = fmaxf(mx, __shfl_xor_sync(~0u, mx, d));
                    mn = fminf(mn, __shfl_xor_sync(~0u, mn, d));
                }
                int jg = by*128 + j;
                g_buf[(size_t)jg*MM + m0 + s*32 + lane] = val;
                if (lane == 0) {
                    atomicMax(&gmax_d[jg], encf(mx));
                    atomicMin(&gmin_d[jg], encf(mn));
                }
            } else {
                int c = by*128 + j;
                int mb = m0 + s*32;
                int img = mb / HWC;
                OUT[(size_t)img*(CC*HWC) + (size_t)c*HWC + (mb - img*HWC) + lane]
                    = val + ps[1536 + c];
            }
        }
    }
}

// ---------------- mid: mn, s, clip, quant params ----------------
__global__ void mid_k(const float* __restrict__ u, const float* __restrict__ cv,
                      const int* __restrict__ abw) {
    __shared__ float mns[CC];
    int t = threadIdx.x;
    float mn = chsum_d[t] * (1.0f / (float)MM);
    mn_d[t] = mn; mns[t] = mn;
    __syncthreads();
    float s = 0.0f;
    #pragma unroll 8
    for (int c = 0; c < CC; c++) s += u[(size_t)c*CC + t] * mns[c];
    s_d[t] = s;
    float c = cv[t]; cvv_d[t] = c;
    int ab = abw ? *abw : 8;
    float dmax = fminf(fmaxf(decf(gmax_d[t]) - s, -c), c);
    float dmin = fminf(fmaxf(decf(gmin_d[t]) - s, -c), c);
    int same = (dmax == dmin) || (ab >= 17);
    float rng = same ? 1.0f : (dmax - dmin);
    float levels = (float)((1 << (same ? 8 : ab)) - 1);
    same_d[t]  = same ? 1.0f : 0.0f;
    dmin_d[t]  = dmin;
    scale_d[t] = levels / rng;
    inv_d[t]   = rng / levels;
}

// ---------------- qsum ----------------
__global__ void __launch_bounds__(512, 2) qsum_k() {
    __shared__ float red[16];
    int j = blockIdx.y;
    float s = s_d[j], dm = dmin_d[j], sc = scale_d[j], iv = inv_d[j],
          cv = cvv_d[j], smf = same_d[j];
    size_t base = (size_t)j*MM + (size_t)blockIdx.x*2048 + threadIdx.x*4;
    float4 v = *(const float4*)(g_buf + base);
    float sum = quant1(v.x, s, dm, sc, iv, cv, smf) + quant1(v.y, s, dm, sc, iv, cv, smf)
              + quant1(v.z, s, dm, sc, iv, cv, smf) + quant1(v.w, s, dm, sc, iv, cv, smf);
    #pragma unroll
    for (int d = 1; d < 32; d <<= 1) sum += __shfl_xor_sync(~0u, sum, d);
    int lane = threadIdx.x & 31, wid = threadIdx.x >> 5;
    if (lane == 0) red[wid] = sum;
    __syncthreads();
    if (threadIdx.x < 16) {
        float r = red[threadIdx.x];
        #pragma unroll
        for (int d = 1; d < 16; d <<= 1) r += __shfl_xor_sync(0xffffu, r, d);
        if (threadIdx.x == 0) atomicAdd(&qsum_d[j], r);
    }
}

// ---------------- bias ----------------
__global__ void bias_k(const float* __restrict__ u) {
    __shared__ float qm[CC];
    int t = threadIdx.x;
    qm[t] = qsum_d[t] * (1.0f / (float)MM);
    __syncthreads();
    float b = 0.0f;
    #pragma unroll 8
    for (int j = 0; j < CC; j++) b += u[(size_t)t*CC + j] * qm[j];
    bias_d[t] = mn_d[t] - b;
}

// ---------------- launcher ----------------
extern "C" void kernel_launch(void* const* d_in, const int* in_sizes, int n_in,
                              void* d_out, int out_size) {
    const float* x  = (const float*)d_in[0];
    const float* u  = (const float*)d_in[1];
    const float* cv = (const float*)d_in[2];
    const int*   ab = (n_in > 3) ? (const int*)d_in[3] : nullptr;
    float* out = (float*)d_out;
    (void)in_sizes; (void)out_size;

    cudaFuncSetAttribute(hgemm_k<0>, cudaFuncAttributeMaxDynamicSharedMemorySize, SMEM_T);
    cudaFuncSetAttribute(hgemm_k<1>, cudaFuncAttributeMaxDynamicSharedMemorySize, SMEM_T);

    prep_k<<<CC + 1, CC>>>(u);
    hgemm_k<0><<<dim3(784, 2), 256, SMEM_T>>>(x, u, nullptr);
    mid_k<<<1, CC>>>(u, cv, ab);
    qsum_k<<<dim3(MM/2048, CC), 512>>>();
    bias_k<<<1, CC>>>(u);
    hgemm_k<1><<<dim3(784, 2), 256, SMEM_T>>>(nullptr, u, out);
}

// round 7
// speedup vs baseline: 1.8603x; 1.8603x over previous
#include <cuda_runtime.h>
#include <cuda_fp16.h>
#include <cstdint>

#define CC 256
#define HWC 3136
#define MM 100352
#define NTILE 784
#define NTH 256
#define STRA 40                 /* halfs per smem row (80B, conflict-free ldmatrix) */
#define STG_AH 0
#define STG_AM 10240
#define STG_BH 20480
#define STG_BM 30720
#define STG_SZ 40960
#define SO_STG 8192
#define SMEM_T (SO_STG + 2*STG_SZ)   /* 90112 */
#define INV2048 (1.0f/2048.0f)

// -------------------- device scratch --------------------
__device__ __align__(16) float  g_buf[(size_t)CC*MM];
__device__ __align__(16) __half ut_hi_d[CC*CC], ut_mid_d[CC*CC];   // GEMM1 B [j][c]
__device__ __align__(16) __half w_hi_d[CC*CC],  w_mid_d[CC*CC];    // GEMM2 B [c][j] (u*iv split)
__device__ float    chsum_d[CC];
__device__ unsigned gmax_d[CC], gmin_d[CC];
__device__ float    mn_d[CC], s_d[CC], dmin_d[CC], scale_d[CC], inv_d[CC], cvv_d[CC];
__device__ float    qsum_d[CC], bias_d[CC], same_d[CC];

// -------------------- helpers --------------------
__device__ __forceinline__ void cp16(uint32_t sdst, const void* g) {
    asm volatile("cp.async.ca.shared.global [%0], [%1], 16;" :: "r"(sdst), "l"(g) : "memory");
}
__device__ __forceinline__ void cp_commit() { asm volatile("cp.async.commit_group;" ::: "memory"); }
__device__ __forceinline__ void cp_wait0()  { asm volatile("cp.async.wait_group 0;" ::: "memory"); }

__device__ __forceinline__ void ldsm4(unsigned* r, uint32_t addr) {
    asm volatile("ldmatrix.sync.aligned.m8n8.x4.shared.b16 {%0,%1,%2,%3}, [%4];"
        : "=r"(r[0]), "=r"(r[1]), "=r"(r[2]), "=r"(r[3]) : "r"(addr));
}
__device__ __forceinline__ void mma16816(float* d, const unsigned* a, const unsigned* b) {
    asm volatile("mma.sync.aligned.m16n8k16.row.col.f32.f16.f16.f32 "
        "{%0,%1,%2,%3}, {%4,%5,%6,%7}, {%8,%9}, {%0,%1,%2,%3};"
        : "+f"(d[0]), "+f"(d[1]), "+f"(d[2]), "+f"(d[3])
        : "r"(a[0]), "r"(a[1]), "r"(a[2]), "r"(a[3]), "r"(b[0]), "r"(b[1]));
}
__device__ __forceinline__ unsigned encf(float f) {
    unsigned u = __float_as_uint(f);
    return (u & 0x80000000u) ? ~u : (u | 0x80000000u);
}
__device__ __forceinline__ float decf(unsigned u) {
    unsigned b = (u & 0x80000000u) ? (u & 0x7FFFFFFFu) : ~u;
    return __uint_as_float(b);
}
__device__ __forceinline__ float quant1(float g, float s, float dm, float sc, float iv,
                                        float cv, float sm) {
    float val = fminf(fmaxf(g - s, -cv), cv);
    float qq  = rintf((val - dm) * sc) * iv + dm;
    return (sm > 0.5f) ? val : qq;
}

// -------------------- prep: split u^T into fp16 hi/mid (scaled), zero accumulators ----
__global__ void prep_k(const float* __restrict__ u) {
    int t = threadIdx.x, b = blockIdx.x;
    if (b < CC) {
        float val = u[(size_t)b*CC + t];          // u[c=b][j=t]
        __half h = __float2half_rn(val);
        __half e = __float2half_rn((val - __half2float(h)) * 2048.0f);
        ut_hi_d[t*CC + b] = h;  ut_mid_d[t*CC + b] = e;   // [j][c] for GEMM1 B
    } else {
        chsum_d[t] = 0.0f; qsum_d[t] = 0.0f;
        gmax_d[t] = 0u; gmin_d[t] = 0xFFFFFFFFu;
    }
}

// -------------------- GEMM --------------------
// MODE 0: g[j][m] = sum_c relu(x[c,m]) * u[c][j]      (3-term split; +chsum, per-j max/min)
// MODE 1: out[c][m] = sum_j w[c][j]*n[j][m] + bias2[c] (2-term: n exact fp16, w split)
template<int MODE>
__global__ void __launch_bounds__(NTH)
mgemm_k(const float* __restrict__ X, float* __restrict__ OUT)
{
    extern __shared__ char smem[];
    const uint32_t sb = (uint32_t)__cvta_generic_to_shared(smem);
    const int tid = threadIdx.x;
    const int lane = tid & 31, w = tid >> 5;
    const int m0 = blockIdx.x * 128;
    const int by = blockIdx.y;                 // n-half (0/1)

    float* ps = (float*)smem;                  // param arrays (MODE 1)
    if (MODE) {
        ps[tid]        = s_d[tid];
        ps[256 + tid]  = dmin_d[tid];
        ps[512 + tid]  = scale_d[tid];
        ps[768 + tid]  = cvv_d[tid];
        ps[1024 + tid] = bias_d[tid];
        __syncthreads();
    }

    const int mg = tid & 15, cp = tid >> 4;    // producer coords: 8-m group, k-pair
    const int mrow = m0 + mg*8;
    size_t abase = 0;
    if (!MODE) {
        int nimg = mrow / HWC;
        abase = (size_t)nimg*(CC*HWC) + (size_t)(mrow - nimg*HWC);
    }

    float v[2][8];

    auto loadA = [&](int kc) {
        #pragma unroll
        for (int cc = 0; cc < 2; cc++) {
            int c = kc*32 + cp*2 + cc;
            const float4* p;
            if (!MODE) p = (const float4*)(X + abase + (size_t)c*HWC);
            else       p = (const float4*)(g_buf + (size_t)c*MM + mrow);
            float4 q0 = p[0], q1 = p[1];
            v[cc][0]=q0.x; v[cc][1]=q0.y; v[cc][2]=q0.z; v[cc][3]=q0.w;
            v[cc][4]=q1.x; v[cc][5]=q1.y; v[cc][6]=q1.z; v[cc][7]=q1.w;
        }
    };
    auto procA = [&](int kc, int st) {
        char* base = smem + SO_STG + st*STG_SZ;
        #pragma unroll
        for (int cc = 0; cc < 2; cc++) {
            int c = kc*32 + cp*2 + cc;
            if (!MODE) {
                float s = 0.f;
                #pragma unroll
                for (int i = 0; i < 8; i++) { v[cc][i] = fmaxf(v[cc][i], 0.f); s += v[cc][i]; }
                s += __shfl_xor_sync(~0u, s, 1); s += __shfl_xor_sync(~0u, s, 2);
                s += __shfl_xor_sync(~0u, s, 4); s += __shfl_xor_sync(~0u, s, 8);
                if (by == 0 && (lane & 15) == 0) atomicAdd(&chsum_d[c], s);
            } else {
                float S=ps[c], DM=ps[256+c], SC=ps[512+c], CV=ps[768+c];
                #pragma unroll
                for (int i = 0; i < 8; i++) {
                    float val = fminf(fmaxf(v[cc][i] - S, -CV), CV);
                    v[cc][i] = rintf((val - DM) * SC);   // integer level, exact in fp16
                }
            }
        }
        if (!MODE) {
            #pragma unroll
            for (int i = 0; i < 8; i++) {
                __half h0 = __float2half_rn(v[0][i]);
                __half h1 = __float2half_rn(v[1][i]);
                __half e0 = __float2half_rn((v[0][i] - __half2float(h0)) * 2048.0f);
                __half e1 = __float2half_rn((v[1][i] - __half2float(h1)) * 2048.0f);
                uint32_t off = (uint32_t)(((mg*8 + i)*STRA + cp*2) * 2);
                *(__half2*)(base + STG_AH + off) = __halves2half2(h0, h1);
                *(__half2*)(base + STG_AM + off) = __halves2half2(e0, e1);
            }
        } else {
            #pragma unroll
            for (int i = 0; i < 8; i++) {
                uint32_t off = (uint32_t)(((mg*8 + i)*STRA + cp*2) * 2);
                *(__half2*)(base + STG_AH + off) =
                    __halves2half2(__float2half_rn(v[0][i]), __float2half_rn(v[1][i]));
            }
        }
    };
    auto prodB = [&](int kc, int st) {
        const __half* srch = MODE ? w_hi_d  : ut_hi_d;
        const __half* srcm = MODE ? w_mid_d : ut_mid_d;
        #pragma unroll
        for (int i = 0; i < 4; i++) {
            int ui = tid + i*NTH;                 // 0..1023
            int ish = (ui < 512);
            int r = (ui & 511) >> 2;              // row 0..127
            int q = ui & 3;
            uint32_t dst = sb + SO_STG + st*STG_SZ + (ish ? STG_BH : STG_BM)
                         + (uint32_t)(r*80 + q*16);
            const __half* s = (ish ? srch : srcm) + (size_t)(by*128 + r)*CC + kc*32 + q*8;
            cp16(dst, s);
        }
    };

    float acch[2][8][4] = {};
    float accm[2][8][4] = {};
    const int wm = (w & 3) * 32;
    const int wn = (w >> 2) * 64;

    prodB(0, 0); cp_commit();
    loadA(0);
    procA(0, 0);

    const int arow = (lane & 15);
    const int asel = (lane >> 4) << 3;
    const int brow = (lane & 7) + ((lane >> 4) << 3);
    const int bsel = ((lane >> 3) & 1) << 3;

    for (int kc = 0; kc < 8; kc++) {
        const int st = kc & 1;
        if (kc < 7) loadA(kc + 1);
        cp_wait0();
        __syncthreads();

        const uint32_t ahb = sb + SO_STG + st*STG_SZ + STG_AH;
        const uint32_t bhb = sb + SO_STG + st*STG_SZ + STG_BH;
        #pragma unroll
        for (int ks = 0; ks < 2; ks++) {
            const int kb = ks*16;
            unsigned ah[2][4], am[2][4];
            #pragma unroll
            for (int mt = 0; mt < 2; mt++) {
                uint32_t ra = ahb + (uint32_t)(((wm + mt*16 + arow)*STRA + kb + asel) * 2);
                ldsm4(ah[mt], ra);
                if (!MODE) ldsm4(am[mt], ra + (STG_AM - STG_AH));
            }
            #pragma unroll
            for (int ng = 0; ng < 4; ng++) {
                uint32_t rb = bhb + (uint32_t)(((wn + ng*16 + brow)*STRA + kb + bsel) * 2);
                unsigned bh[4], bm[4];
                ldsm4(bh, rb);
                ldsm4(bm, rb + (STG_BM - STG_BH));
                #pragma unroll
                for (int mt = 0; mt < 2; mt++) {
                    if (!MODE) {
                        mma16816(acch[mt][ng*2],     ah[mt], bh);
                        mma16816(acch[mt][ng*2 + 1], ah[mt], bh + 2);
                        mma16816(accm[mt][ng*2],     ah[mt], bm);
                        mma16816(accm[mt][ng*2 + 1], ah[mt], bm + 2);
                        mma16816(accm[mt][ng*2],     am[mt], bh);
                        mma16816(accm[mt][ng*2 + 1], am[mt], bh + 2);
                    } else {
                        // n exact; w = w_hi + w_mid, both into same acc
                        mma16816(acch[mt][ng*2],     ah[mt], bh);
                        mma16816(acch[mt][ng*2 + 1], ah[mt], bh + 2);
                        mma16816(acch[mt][ng*2],     ah[mt], bm);
                        mma16816(acch[mt][ng*2 + 1], ah[mt], bm + 2);
                    }
                }
            }
        }
        if (kc < 7) { procA(kc + 1, st ^ 1); prodB(kc + 1, st ^ 1); cp_commit(); }
    }
    __syncthreads();   // stage buffers free -> reuse as transpose scratch

    float* scr = (float*)(smem + SO_STG) + w * (64*36);
    #pragma unroll
    for (int mt = 0; mt < 2; mt++)
        #pragma unroll
        for (int nt = 0; nt < 8; nt++)
            #pragma unroll
            for (int i = 0; i < 4; i++) {
                int nl = nt*8 + (lane & 3)*2 + (i & 1);
                int ml = mt*16 + (lane >> 2) + ((i >> 1) << 3);
                scr[nl*36 + ml] = MODE ? acch[mt][nt][i]
                                       : acch[mt][nt][i] + accm[mt][nt][i] * INV2048;
            }
    __syncwarp();

    if (!MODE) {
        #pragma unroll 4
        for (int r = 0; r < 64; r++) {
            int j = by*128 + wn + r;
            float val = scr[r*36 + lane];
            float mx = val, mn = val;
            #pragma unroll
            for (int d = 1; d < 32; d <<= 1) {
                mx = fmaxf(mx, __shfl_xor_sync(~0u, mx, d));
                mn = fminf(mn, __shfl_xor_sync(~0u, mn, d));
            }
            g_buf[(size_t)j*MM + m0 + wm + lane] = val;
            if (lane == 0) {
                atomicMax(&gmax_d[j], encf(mx));
                atomicMin(&gmin_d[j], encf(mn));
            }
        }
    } else {
        int mstart = m0 + wm;
        int nimg = mstart / HWC;
        size_t base = (size_t)nimg*(CC*HWC) + (size_t)(mstart - nimg*HWC);
        #pragma unroll 4
        for (int r = 0; r < 64; r++) {
            int c = by*128 + wn + r;
            OUT[base + (size_t)c*HWC + lane] = scr[r*36 + lane] + ps[1024 + c];
        }
    }
}

// -------------------- mid: mn, s, clip, quant params --------------------
__global__ void mid_k(const float* __restrict__ u, const float* __restrict__ cv,
                      const int* __restrict__ abw) {
    __shared__ float mns[CC];
    int t = threadIdx.x;
    float mn = chsum_d[t] * (1.0f / (float)MM);
    mn_d[t] = mn; mns[t] = mn;
    __syncthreads();
    float s = 0.0f;
    #pragma unroll 8
    for (int c = 0; c < CC; c++) s += u[(size_t)c*CC + t] * mns[c];
    s_d[t] = s;
    float c = cv[t]; cvv_d[t] = c;
    int ab = abw ? *abw : 8;
    float dmax = fminf(fmaxf(decf(gmax_d[t]) - s, -c), c);
    float dmin = fminf(fmaxf(decf(gmin_d[t]) - s, -c), c);
    int same = (dmax == dmin) || (ab >= 17);
    float rng = same ? 1.0f : (dmax - dmin);
    float levels = (float)((1 << (same ? 8 : ab)) - 1);
    same_d[t]  = same ? 1.0f : 0.0f;
    dmin_d[t]  = dmin;
    scale_d[t] = levels / rng;
    inv_d[t]   = rng / levels;
}

// -------------------- wsplit: w = u*iv, split fp16 hi/mid (unscaled residual) ----
__global__ void wsplit_k(const float* __restrict__ u) {
    int c = blockIdx.x, j = threadIdx.x;
    float wv = u[(size_t)c*CC + j] * inv_d[j];
    __half h = __float2half_rn(wv);
    __half e = __float2half_rn(wv - __half2float(h));
    w_hi_d [c*CC + j] = h;
    w_mid_d[c*CC + j] = e;
}

// -------------------- qsum: read-only quant reduction --------------------
__global__ void __launch_bounds__(512, 2) qsum_k() {
    __shared__ float red[16];
    int j = blockIdx.y;
    float s = s_d[j], dm = dmin_d[j], sc = scale_d[j], iv = inv_d[j],
          cv = cvv_d[j], smf = same_d[j];
    size_t base = (size_t)j*MM + (size_t)blockIdx.x*2048 + threadIdx.x*4;
    float4 v = *(const float4*)(g_buf + base);
    float sum = quant1(v.x, s, dm, sc, iv, cv, smf) + quant1(v.y, s, dm, sc, iv, cv, smf)
              + quant1(v.z, s, dm, sc, iv, cv, smf) + quant1(v.w, s, dm, sc, iv, cv, smf);
    #pragma unroll
    for (int d = 1; d < 32; d <<= 1) sum += __shfl_xor_sync(~0u, sum, d);
    int lane = threadIdx.x & 31, wid = threadIdx.x >> 5;
    if (lane == 0) red[wid] = sum;
    __syncthreads();
    if (threadIdx.x < 16) {
        float r = red[threadIdx.x];
        #pragma unroll
        for (int d = 1; d < 16; d <<= 1) r += __shfl_xor_sync(0xffffu, r, d);
        if (threadIdx.x == 0) atomicAdd(&qsum_d[j], r);
    }
}

// -------------------- bias2[c] = mn[c] + sum_j u[c][j]*(dmin[j] - qmean[j]) ----
__global__ void bias_k(const float* __restrict__ u) {
    __shared__ float dq[CC];
    int t = threadIdx.x;
    dq[t] = dmin_d[t] - qsum_d[t] * (1.0f / (float)MM);
    __syncthreads();
    float b = 0.0f;
    #pragma unroll 8
    for (int j = 0; j < CC; j++) b += u[(size_t)t*CC + j] * dq[j];
    bias_d[t] = mn_d[t] + b;
}

// -------------------- launcher --------------------
extern "C" void kernel_launch(void* const* d_in, const int* in_sizes, int n_in,
                              void* d_out, int out_size) {
    const float* x  = (const float*)d_in[0];
    const float* u  = (const float*)d_in[1];
    const float* cv = (const float*)d_in[2];
    const int*   ab = (n_in > 3) ? (const int*)d_in[3] : nullptr;
    float* out = (float*)d_out;
    (void)in_sizes; (void)out_size;

    cudaFuncSetAttribute(mgemm_k<0>, cudaFuncAttributeMaxDynamicSharedMemorySize, SMEM_T);
    cudaFuncSetAttribute(mgemm_k<1>, cudaFuncAttributeMaxDynamicSharedMemorySize, SMEM_T);

    prep_k<<<CC + 1, CC>>>(u);
    mgemm_k<0><<<dim3(NTILE, 2), NTH, SMEM_T>>>(x, nullptr);
    mid_k<<<1, CC>>>(u, cv, ab);
    wsplit_k<<<CC, CC>>>(u);
    qsum_k<<<dim3(MM/2048, CC), 512>>>();
    bias_k<<<1, CC>>>(u);
    mgemm_k<1><<<dim3(NTILE, 2), NTH, SMEM_T>>>(nullptr, out);
}